// round 15
// baseline (speedup 1.0000x reference)
#include <cuda_runtime.h>
#include <cuda_fp16.h>
#include <math.h>
#include <stdint.h>

#define N_TOK  100000
#define C      128
#define NT     128
#define NTILES ((N_TOK + NT - 1) / NT)            // 782  (GEMM2 tiles)
#define NBLK   148
#define CH     64
#define NCH    ((N_TOK + CH - 1) / CH)            // 1563 (GEMM1 chunks)

typedef unsigned long long ull;

// ---------------- scratch ----------------------------------------------------
__device__ float g_part[NBLK * C * C];
__device__ float g_spec[C * C];
__device__ float g_mixed[C * C];                 // mixed [o][k]
__device__ __half g_Uhi[(size_t)N_TOK * C];      // pre-split U (hi halves)
__device__ __half g_Ulo[(size_t)N_TOK * C];      // pre-split U (lo halves)
__device__ float g_pm[C * NBLK];
__device__ float g_ps[C * NBLK];
__device__ float g_max[C];
__device__ float g_sinv[C];

__device__ __forceinline__ void comb(float& m, float& s, float m2, float s2) {
    float M = fmaxf(m, m2);
    float S = 0.f;
    if (m  > -INFINITY) S += s  * __expf(m  - M);
    if (m2 > -INFINITY) S += s2 * __expf(m2 - M);
    m = M; s = S;
}

// ---------------- fp16 warp-MMA helpers --------------------------------------
__device__ __forceinline__ uint32_t smem_u32(const void* p) {
    uint32_t a;
    asm("{ .reg .u64 t; cvta.to.shared.u64 t, %1; cvt.u32.u64 %0, t; }"
        : "=r"(a) : "l"(p));
    return a;
}
__device__ __forceinline__ void ldsm4(uint32_t& r0, uint32_t& r1,
                                      uint32_t& r2, uint32_t& r3, uint32_t addr) {
    asm volatile("ldmatrix.sync.aligned.m8n8.x4.shared.b16 {%0,%1,%2,%3}, [%4];"
                 : "=r"(r0), "=r"(r1), "=r"(r2), "=r"(r3) : "r"(addr));
}
__device__ __forceinline__ void ldsm4t(uint32_t& r0, uint32_t& r1,
                                       uint32_t& r2, uint32_t& r3, uint32_t addr) {
    asm volatile("ldmatrix.sync.aligned.m8n8.x4.trans.shared.b16 {%0,%1,%2,%3}, [%4];"
                 : "=r"(r0), "=r"(r1), "=r"(r2), "=r"(r3) : "r"(addr));
}
__device__ __forceinline__ void mma_f16(float* d, const uint32_t* a,
                                        const uint32_t* b) {
    asm volatile(
        "mma.sync.aligned.m16n8k16.row.col.f32.f16.f16.f32 "
        "{%0,%1,%2,%3}, {%4,%5,%6,%7}, {%8,%9}, {%0,%1,%2,%3};"
        : "+f"(d[0]), "+f"(d[1]), "+f"(d[2]), "+f"(d[3])
        : "r"(a[0]), "r"(a[1]), "r"(a[2]), "r"(a[3]), "r"(b[0]), "r"(b[1]));
}
__device__ __forceinline__ uint32_t h2_bits(__half2 h) {
    union { __half2 h; uint32_t u; } c; c.h = h; return c.u;
}
__device__ __forceinline__ void split4(float4 v, uint2& H, uint2& L) {
    __half2 h01 = __float22half2_rn(make_float2(v.x, v.y));
    __half2 h23 = __float22half2_rn(make_float2(v.z, v.w));
    float2 b01 = __half22float2(h01);
    float2 b23 = __half22float2(h23);
    __half2 l01 = __float22half2_rn(make_float2(v.x - b01.x, v.y - b01.y));
    __half2 l23 = __float22half2_rn(make_float2(v.z - b23.x, v.w - b23.y));
    H.x = h2_bits(h01); H.y = h2_bits(h23);
    L.x = h2_bits(l01); L.y = h2_bits(l23);
}
#define ROWH 136
#define ROWB 272

// ---------------- 1) GEMM1: persistent fp16-split, fused; exports U halves ---
// spec[k=128][i=128] = sum_n U[n][k]*x[n][i]; MMA-K = n (trans ldmatrix loads)
#define G1_UH  0
#define G1_UL  17408
#define G1_XH  34816
#define G1_XL  52224
#define G1_RAW 69632
#define G1_SM  200704

__global__ void __launch_bounds__(512, 1) k_gemm1_mma(const float* __restrict__ U,
                                                      const float* __restrict__ x) {
    extern __shared__ char smem[];
    uint32_t sb = smem_u32(smem);
    int tid = threadIdx.x, wid = tid >> 5, lid = tid & 31;
    int bid = blockIdx.x;
    int kb = (wid & 3) * 32;
    int ib = (wid >> 2) * 32;

    int arow = (lid & 7) + ((lid >> 4) & 1) * 8;
    int acol = ((lid >> 3) & 1) * 8;
    int brow = (lid & 7) + ((lid >> 3) & 1) * 8;
    int bcol = ((lid >> 4) & 1) * 8;

    auto cp_chunk = [&](int ch, int buf) {
        int n0 = ch * CH;
        int nv = min(CH, N_TOK - n0);
#pragma unroll
        for (int i = 0; i < 4; i++) {
            int f = i * 512 + tid;
            int r = f >> 5, c4 = f & 31;
            int ok = (r < nv);
            const float* gu = U + (size_t)(n0 + (ok ? r : 0)) * C + 4 * c4;
            const float* gx = x + (size_t)(n0 + (ok ? r : 0)) * C + 4 * c4;
            uint32_t du = sb + G1_RAW + buf * 65536 + f * 16;
            int sz = ok ? 16 : 0;
            asm volatile("cp.async.cg.shared.global [%0], [%1], 16, %2;"
                         :: "r"(du), "l"(gu), "r"(sz) : "memory");
            asm volatile("cp.async.cg.shared.global [%0], [%1], 16, %2;"
                         :: "r"(du + 32768u), "l"(gx), "r"(sz) : "memory");
        }
        asm volatile("cp.async.commit_group;" ::: "memory");
    };

    float d[2][4][4];
#pragma unroll
    for (int mf = 0; mf < 2; mf++)
#pragma unroll
        for (int nf = 0; nf < 4; nf++)
#pragma unroll
            for (int q = 0; q < 4; q++) d[mf][nf][q] = 0.f;

    cp_chunk(bid, 0);
    int it = 0;
    for (int ch = bid; ch < NCH; ch += NBLK, it++) {
        int buf = it & 1;
        if (ch + NBLK < NCH) {
            cp_chunk(ch + NBLK, buf ^ 1);
            asm volatile("cp.async.wait_group 1;" ::: "memory");
        } else {
            asm volatile("cp.async.wait_group 0;" ::: "memory");
        }
        __syncthreads();

#pragma unroll
        for (int i = 0; i < 4; i++) {
            int f = i * 512 + tid;
            int r = f >> 5, c4 = f & 31;
            float4 vu = *(const float4*)(smem + G1_RAW + buf * 65536 + f * 16);
            float4 vx = *(const float4*)(smem + G1_RAW + buf * 65536 + 32768 + f * 16);
            uint2 H, L;
            split4(vu, H, L);
            *(uint2*)(smem + G1_UH + r * ROWB + 8 * c4) = H;
            *(uint2*)(smem + G1_UL + r * ROWB + 8 * c4) = L;
            split4(vx, H, L);
            *(uint2*)(smem + G1_XH + r * ROWB + 8 * c4) = H;
            *(uint2*)(smem + G1_XL + r * ROWB + 8 * c4) = L;
        }
        __syncthreads();

        // fused 3-product loop
#pragma unroll
        for (int ks = 0; ks < 4; ks++) {
            int t0 = 16 * ks;
            uint32_t uh[2][4], ul[2][4];
#pragma unroll
            for (int mf = 0; mf < 2; mf++) {
                uint32_t off = ((t0 + arow) * ROWH + kb + mf * 16 + acol) * 2;
                ldsm4t(uh[mf][0], uh[mf][1], uh[mf][2], uh[mf][3],
                       sb + G1_UH + off);
                ldsm4t(ul[mf][0], ul[mf][1], ul[mf][2], ul[mf][3],
                       sb + G1_UL + off);
            }
#pragma unroll
            for (int p4 = 0; p4 < 2; p4++) {
                uint32_t off = ((t0 + brow) * ROWH + ib + p4 * 16 + bcol) * 2;
                uint32_t xh[4], xl[4];
                ldsm4t(xh[0], xh[1], xh[2], xh[3], sb + G1_XH + off);
                ldsm4t(xl[0], xl[1], xl[2], xl[3], sb + G1_XL + off);
#pragma unroll
                for (int mf = 0; mf < 2; mf++)
#pragma unroll
                    for (int n2 = 0; n2 < 2; n2++) {
                        float* dd = d[mf][2 * p4 + n2];
                        mma_f16(dd, uh[mf], &xh[2 * n2]);
                        mma_f16(dd, uh[mf], &xl[2 * n2]);
                        mma_f16(dd, ul[mf], &xh[2 * n2]);
                    }
            }
        }

        // export split U halves for gemm3 (reads smem into regs, then STG)
        {
            int n0 = ch * CH;
            int nv = min(CH, N_TOK - n0);
#pragma unroll
            for (int i = 0; i < 2; i++) {
                int f = i * 512 + tid;            // 0..1023
                int r = f >> 4, c = f & 15;       // row, 16B chunk
                if (r < nv) {
                    uint4 vh = *(const uint4*)(smem + G1_UH + r * ROWB + 16 * c);
                    uint4 vl = *(const uint4*)(smem + G1_UL + r * ROWB + 16 * c);
                    *(uint4*)((char*)(g_Uhi + (size_t)(n0 + r) * C) + 16 * c) = vh;
                    *(uint4*)((char*)(g_Ulo + (size_t)(n0 + r) * C) + 16 * c) = vl;
                }
            }
        }
    }

    float* dst = g_part + (size_t)bid * (C * C);
#pragma unroll
    for (int mf = 0; mf < 2; mf++)
#pragma unroll
        for (int nf = 0; nf < 4; nf++) {
            int row = kb + mf * 16 + (lid >> 2);
            int col = ib + nf * 8 + 2 * (lid & 3);
            *(float2*)&dst[row * C + col] =
                make_float2(d[mf][nf][0], d[mf][nf][1]);
            *(float2*)&dst[(row + 8) * C + col] =
                make_float2(d[mf][nf][2], d[mf][nf][3]);
        }
}

// ---------------- 2) reduce partials -> g_spec -------------------------------
__global__ void k_rsum() {
    int j = blockIdx.x * 256 + threadIdx.x;
    float s0 = 0.f, s1 = 0.f, s2 = 0.f, s3 = 0.f;
#pragma unroll 1
    for (int b = 0; b < NBLK; b += 4) {
        s0 += g_part[(b + 0) * (C * C) + j];
        s1 += g_part[(b + 1) * (C * C) + j];
        s2 += g_part[(b + 2) * (C * C) + j];
        s3 += g_part[(b + 3) * (C * C) + j];
    }
    g_spec[j] = (s0 + s1) + (s2 + s3);
}

// ---------------- 3) mixed -> g_mixed[o][k] ----------------------------------
__global__ void __launch_bounds__(256) k_mixed_w(const float* __restrict__ coeffs) {
    int gw   = blockIdx.x * 8 + (threadIdx.x >> 5);
    int lane = threadIdx.x & 31;
    int o = gw >> 5, k0 = (gw & 31) * 4;
    float s[4];
#pragma unroll
    for (int kk = 0; kk < 4; kk++) {
        int k = k0 + kk;
        float4 a  = ((const float4*)(coeffs + (((size_t)o * C + k) << 7)))[lane];
        float4 bv = ((const float4*)(g_spec + (k << 7)))[lane];
        s[kk] = a.x * bv.x + a.y * bv.y + a.z * bv.z + a.w * bv.w;
    }
#pragma unroll
    for (int off = 16; off; off >>= 1)
#pragma unroll
        for (int kk = 0; kk < 4; kk++)
            s[kk] += __shfl_xor_sync(0xffffffffu, s[kk], off);
    if (lane == 0) {
#pragma unroll
        for (int kk = 0; kk < 4; kk++) g_mixed[(size_t)o * C + k0 + kk] = s[kk];
    }
}

// ---------------- 4) GEMM2: quad-partitioned, pre-split B, double-buffered ---
#define A_HI 0
#define A_LO 34816
#define BBUF0 69632
#define BBUF1 139264
#define BLO_OFF 34816              // lo region offset inside a B buffer
#define SM_TOT 208896
#define SUM_THR (-15.0f)
#define QCH 8704                  // per-quad B chunk bytes (32 rows * 272)
#define SROW 528                  // staging row stride bytes (132 floats)

__global__ void __launch_bounds__(512, 1) k_gemm3_p(const float* __restrict__ U,
                                                    float* __restrict__ out) {
    extern __shared__ char smem[];
    uint32_t sb = smem_u32(smem);
    __shared__ float red_m[4][C], red_s[4][C];
    int tid = threadIdx.x, wid = tid >> 5, lid = tid & 31;
    int bid = blockIdx.x;
    int quad = tid >> 7;                // 0..3  (n-slice owner)
    int qtid = tid & 127;
    int ob  = (wid & 3) * 32;           // warp o-base
    int nbw = quad * 32;                // quad n-base

    int arow_l = (lid & 7) + ((lid >> 3) & 1) * 8;
    int acol_l = ((lid >> 4) & 1) * 8;
    int brow_l = (lid & 7) + ((lid >> 4) & 1) * 8;
    int bcol_l = ((lid >> 3) & 1) * 8;

#define QBAR() asm volatile("bar.sync %0, 128;" :: "r"(1 + quad) : "memory")
    auto stg_ptr = [&](int bbase, int rr, int o) -> float* {
        int base = bbase + ((rr & 16) ? BLO_OFF : 0) + QCH * quad
                 + (rr & 15) * SROW;
        return (float*)(smem + base) + o;
    };

    // cp pre-split halves straight into a B buffer (quad rows only)
    auto cp_tile = [&](int t, int bbase) {
        int n0 = t * NT;
        int nvalid = min(NT, N_TOK - n0);
#pragma unroll
        for (int i = 0; i < 4; i++) {
            int f = i * 128 + qtid;             // 0..511 within quad
            int r = nbw + (f >> 4), c = f & 15; // row, 16B chunk (16 per row)
            int ok = (r < nvalid);
            const char* sh = (const char*)(g_Uhi + (size_t)(n0 + (ok ? r : 0)) * C) + 16 * c;
            const char* sl = (const char*)(g_Ulo + (size_t)(n0 + (ok ? r : 0)) * C) + 16 * c;
            uint32_t dh = sb + bbase + r * ROWB + 16 * c;
            int sz = ok ? 16 : 0;
            asm volatile("cp.async.cg.shared.global [%0], [%1], 16, %2;"
                         :: "r"(dh), "l"(sh), "r"(sz) : "memory");
            asm volatile("cp.async.cg.shared.global [%0], [%1], 16, %2;"
                         :: "r"(dh + BLO_OFF), "l"(sl), "r"(sz) : "memory");
        }
        asm volatile("cp.async.commit_group;" ::: "memory");
    };

    if (bid < NTILES) cp_tile(bid, BBUF0);
    // A fill (block-wide, once)
#pragma unroll
    for (int i = 0; i < 8; i++) {
        int f = i * 512 + tid;
        int r = f >> 5, c4 = f & 31;
        float4 v = ((const float4*)(g_mixed + (size_t)r * C))[c4];
        uint2 H, L;
        split4(v, H, L);
        *(uint2*)(smem + A_HI + r * ROWB + 8 * c4) = H;
        *(uint2*)(smem + A_LO + r * ROWB + 8 * c4) = L;
    }
    __syncthreads();                     // A visible to all quads

    float pm[4] = { -INFINITY, -INFINITY, -INFINITY, -INFINITY };
    float ps[4] = { 0.f, 0.f, 0.f, 0.f };

    int buf = 0;
    for (int t = bid; t < NTILES; t += NBLK) {
        int n0 = t * NT;
        int nvalid = min(NT, N_TOK - n0);
        int bbase = buf ? BBUF1 : BBUF0;
        int nbase = buf ? BBUF0 : BBUF1;

        asm volatile("cp.async.wait_group 0;" ::: "memory");
        QBAR();                          // B[buf] visible; prev stg reads done

        if (t + NBLK < NTILES) cp_tile(t + NBLK, nbase);

        float d[2][4][4];
#pragma unroll
        for (int mf = 0; mf < 2; mf++)
#pragma unroll
            for (int nf = 0; nf < 4; nf++)
#pragma unroll
                for (int q = 0; q < 4; q++) d[mf][nf][q] = 0.f;

        // fused 3-product loop
#pragma unroll
        for (int ks = 0; ks < 8; ks++) {
            int k0 = 16 * ks;
            uint32_t ah[2][4], al[2][4];
#pragma unroll
            for (int mf = 0; mf < 2; mf++) {
                uint32_t off = ((ob + mf * 16 + arow_l) * ROWH + k0 + acol_l) * 2;
                ldsm4(ah[mf][0], ah[mf][1], ah[mf][2], ah[mf][3], sb + A_HI + off);
                ldsm4(al[mf][0], al[mf][1], al[mf][2], al[mf][3], sb + A_LO + off);
            }
#pragma unroll
            for (int p4 = 0; p4 < 2; p4++) {
                uint32_t off = ((nbw + p4 * 16 + brow_l) * ROWH + k0 + bcol_l) * 2;
                uint32_t bh[4], bl[4];
                ldsm4(bh[0], bh[1], bh[2], bh[3], sb + bbase + off);
                ldsm4(bl[0], bl[1], bl[2], bl[3], sb + bbase + BLO_OFF + off);
#pragma unroll
                for (int mf = 0; mf < 2; mf++)
#pragma unroll
                    for (int n2 = 0; n2 < 2; n2++) {
                        float* dd = d[mf][2 * p4 + n2];
                        mma_f16(dd, ah[mf], &bh[2 * n2]);
                        mma_f16(dd, ah[mf], &bl[2 * n2]);
                        mma_f16(dd, al[mf], &bh[2 * n2]);
                    }
            }
        }
        QBAR();                          // quad MMA reads done before staging

        // softmax partials (thresholded exp; padded logits = 0 vanish)
#pragma unroll
        for (int mf = 0; mf < 2; mf++)
#pragma unroll
            for (int h = 0; h < 2; h++) {
                int q = 2 * mf + h;
                float mt = -INFINITY;
#pragma unroll
                for (int nf = 0; nf < 4; nf++)
                    mt = fmaxf(mt, fmaxf(d[mf][nf][2 * h], d[mf][nf][2 * h + 1]));
                if (mt > pm[q]) {
                    ps[q] *= __expf(pm[q] - mt);
                    pm[q] = mt;
                }
                float m = pm[q];
#pragma unroll
                for (int nf = 0; nf < 4; nf++) {
                    float t0 = d[mf][nf][2 * h] - m;
                    float t1 = d[mf][nf][2 * h + 1] - m;
                    if (t0 > SUM_THR) ps[q] += __expf(t0);
                    if (t1 > SUM_THR) ps[q] += __expf(t1);
                }
            }

        // stage logits [rr][o] into the quad's OWN rows of B[buf]
#pragma unroll
        for (int mf = 0; mf < 2; mf++)
#pragma unroll
            for (int nf = 0; nf < 4; nf++) {
                int rr = nf * 8 + 2 * (lid & 3);
                int o  = ob + mf * 16 + (lid >> 2);
                *stg_ptr(bbase, rr,     o)     = d[mf][nf][0];
                *stg_ptr(bbase, rr + 1, o)     = d[mf][nf][1];
                *stg_ptr(bbase, rr,     o + 8) = d[mf][nf][2];
                *stg_ptr(bbase, rr + 1, o + 8) = d[mf][nf][3];
            }
        QBAR();                          // staging complete within quad

        // coalesced logit store (quad rows)
#pragma unroll
        for (int i = 0; i < 8; i++) {
            int f = i * 128 + qtid;
            int rr = f >> 5, c4 = f & 31;
            int r = nbw + rr;
            if (r < nvalid) {
                float4 v = *(const float4*)stg_ptr(bbase, rr, 4 * c4);
                ((float4*)(out + (size_t)(n0 + r) * C))[c4] = v;
            }
        }
        buf ^= 1;
    }

    // ---- per-block softmax partials ----
#pragma unroll
    for (int off = 1; off <= 2; off <<= 1) {
#pragma unroll
        for (int q = 0; q < 4; q++) {
            float m2 = __shfl_xor_sync(0xffffffffu, pm[q], off);
            float s2 = __shfl_xor_sync(0xffffffffu, ps[q], off);
            comb(pm[q], ps[q], m2, s2);
        }
    }
    if ((lid & 3) == 0) {
#pragma unroll
        for (int q = 0; q < 4; q++) {
            int o = ob + (q >> 1) * 16 + (q & 1) * 8 + (lid >> 2);
            red_m[quad][o] = pm[q];
            red_s[quad][o] = ps[q];
        }
    }
    __syncthreads();
    if (tid < C) {
        float M = red_m[0][tid], S = red_s[0][tid];
        comb(M, S, red_m[1][tid], red_s[1][tid]);
        comb(M, S, red_m[2][tid], red_s[2][tid]);
        comb(M, S, red_m[3][tid], red_s[3][tid]);
        g_pm[(size_t)tid * NBLK + bid] = M;
        g_ps[(size_t)tid * NBLK + bid] = S;
    }
#undef QBAR
}

// ---------------- 5) combine softmax partials --------------------------------
__global__ void k_softmax_par() {
    int o = blockIdx.x;
    float M = -INFINITY, S = 0.f;
    for (int b = threadIdx.x; b < NBLK; b += 256)
        comb(M, S, g_pm[(size_t)o * NBLK + b], g_ps[(size_t)o * NBLK + b]);
#pragma unroll
    for (int off = 16; off; off >>= 1) {
        float m2 = __shfl_xor_sync(0xffffffffu, M, off);
        float s2 = __shfl_xor_sync(0xffffffffu, S, off);
        comb(M, S, m2, s2);
    }
    __shared__ float sm[8], ss[8];
    int wq = threadIdx.x >> 5, lane = threadIdx.x & 31;
    if (lane == 0) { sm[wq] = M; ss[wq] = S; }
    __syncthreads();
    if (threadIdx.x == 0) {
#pragma unroll
        for (int i = 1; i < 8; i++) comb(sm[0], ss[0], sm[i], ss[i]);
        g_max[o]  = sm[0];
        g_sinv[o] = 1.0f / ss[0];
    }
}

// ---------------- 6) final: thresholded exp + normalize ----------------------
__global__ void k_final2(float* __restrict__ out) {
    int base = blockIdx.x * 512 + threadIdx.x;
#pragma unroll
    for (int h = 0; h < 2; h++) {
        int f = base + h * 256;
        float4 v = ((const float4*)out)[f];
        int og = f & 31;
        float4 M = ((const float4*)g_max)[og];
        float4 I = ((const float4*)g_sinv)[og];
        float t0 = v.x - M.x, t1 = v.y - M.y, t2 = v.z - M.z, t3 = v.w - M.w;
        v.x = (t0 > -87.f) ? __expf(t0) * I.x : 0.f;
        v.y = (t1 > -87.f) ? __expf(t1) * I.y : 0.f;
        v.z = (t2 > -87.f) ? __expf(t2) * I.z : 0.f;
        v.w = (t3 > -87.f) ? __expf(t3) * I.w : 0.f;
        ((float4*)out)[f] = v;
    }
}

// ---------------- launcher ---------------------------------------------------
extern "C" void kernel_launch(void* const* d_in, const int* in_sizes, int n_in,
                              void* d_out, int out_size) {
    const float* x      = (const float*)d_in[0];
    const float* U      = (const float*)d_in[1];
    const float* coeffs = (const float*)d_in[2];
    float* out = (float*)d_out;

    cudaFuncSetAttribute(k_gemm1_mma, cudaFuncAttributeMaxDynamicSharedMemorySize,
                         G1_SM);
    cudaFuncSetAttribute(k_gemm3_p, cudaFuncAttributeMaxDynamicSharedMemorySize,
                         SM_TOT);

    k_gemm1_mma<<<NBLK, 512, G1_SM>>>(U, x);
    k_rsum<<<64, 256>>>();
    k_mixed_w<<<512, 256>>>(coeffs);
    k_gemm3_p<<<NBLK, 512, SM_TOT>>>(U, out);
    k_softmax_par<<<C, 256>>>();
    k_final2<<<N_TOK * C / 4 / 512, 256>>>(out);
}

// round 16
// speedup vs baseline: 1.0023x; 1.0023x over previous
#include <cuda_runtime.h>
#include <cuda_fp16.h>
#include <math.h>
#include <stdint.h>

#define N_TOK  100000
#define C      128
#define NT     128
#define NTILES ((N_TOK + NT - 1) / NT)            // 782  (GEMM2 tiles)
#define NBLK   148
#define CH     64
#define NCH    ((N_TOK + CH - 1) / CH)            // 1563 (GEMM1 chunks)

typedef unsigned long long ull;

// ---------------- scratch ----------------------------------------------------
__device__ float g_part[NBLK * C * C];
__device__ float g_spec[C * C];
__device__ float g_mixed[C * C];                 // mixed [o][k]
__device__ __half g_Uhi[(size_t)N_TOK * C];      // pre-split U (hi halves)
__device__ __half g_Ulo[(size_t)N_TOK * C];      // pre-split U (lo halves)
__device__ float g_pm[C * NBLK];
__device__ float g_ps[C * NBLK];
__device__ float g_max[C];
__device__ float g_sinv[C];

__device__ __forceinline__ void comb(float& m, float& s, float m2, float s2) {
    float M = fmaxf(m, m2);
    float S = 0.f;
    if (m  > -INFINITY) S += s  * __expf(m  - M);
    if (m2 > -INFINITY) S += s2 * __expf(m2 - M);
    m = M; s = S;
}

// ---------------- fp16 warp-MMA helpers --------------------------------------
__device__ __forceinline__ uint32_t smem_u32(const void* p) {
    uint32_t a;
    asm("{ .reg .u64 t; cvta.to.shared.u64 t, %1; cvt.u32.u64 %0, t; }"
        : "=r"(a) : "l"(p));
    return a;
}
__device__ __forceinline__ void ldsm4(uint32_t& r0, uint32_t& r1,
                                      uint32_t& r2, uint32_t& r3, uint32_t addr) {
    asm volatile("ldmatrix.sync.aligned.m8n8.x4.shared.b16 {%0,%1,%2,%3}, [%4];"
                 : "=r"(r0), "=r"(r1), "=r"(r2), "=r"(r3) : "r"(addr));
}
__device__ __forceinline__ void ldsm4t(uint32_t& r0, uint32_t& r1,
                                       uint32_t& r2, uint32_t& r3, uint32_t addr) {
    asm volatile("ldmatrix.sync.aligned.m8n8.x4.trans.shared.b16 {%0,%1,%2,%3}, [%4];"
                 : "=r"(r0), "=r"(r1), "=r"(r2), "=r"(r3) : "r"(addr));
}
__device__ __forceinline__ void mma_f16(float* d, const uint32_t* a,
                                        const uint32_t* b) {
    asm volatile(
        "mma.sync.aligned.m16n8k16.row.col.f32.f16.f16.f32 "
        "{%0,%1,%2,%3}, {%4,%5,%6,%7}, {%8,%9}, {%0,%1,%2,%3};"
        : "+f"(d[0]), "+f"(d[1]), "+f"(d[2]), "+f"(d[3])
        : "r"(a[0]), "r"(a[1]), "r"(a[2]), "r"(a[3]), "r"(b[0]), "r"(b[1]));
}
__device__ __forceinline__ uint32_t h2_bits(__half2 h) {
    union { __half2 h; uint32_t u; } c; c.h = h; return c.u;
}
__device__ __forceinline__ void split4(float4 v, uint2& H, uint2& L) {
    __half2 h01 = __float22half2_rn(make_float2(v.x, v.y));
    __half2 h23 = __float22half2_rn(make_float2(v.z, v.w));
    float2 b01 = __half22float2(h01);
    float2 b23 = __half22float2(h23);
    __half2 l01 = __float22half2_rn(make_float2(v.x - b01.x, v.y - b01.y));
    __half2 l23 = __float22half2_rn(make_float2(v.z - b23.x, v.w - b23.y));
    H.x = h2_bits(h01); H.y = h2_bits(h23);
    L.x = h2_bits(l01); L.y = h2_bits(l23);
}
#define ROWH 136
#define ROWB 272

// ---------------- 1) GEMM1: persistent fp16-split, fused; exports U halves ---
#define G1_UH  0
#define G1_UL  17408
#define G1_XH  34816
#define G1_XL  52224
#define G1_RAW 69632
#define G1_SM  200704

__global__ void __launch_bounds__(512, 1) k_gemm1_mma(const float* __restrict__ U,
                                                      const float* __restrict__ x) {
    extern __shared__ char smem[];
    uint32_t sb = smem_u32(smem);
    int tid = threadIdx.x, wid = tid >> 5, lid = tid & 31;
    int bid = blockIdx.x;
    int kb = (wid & 3) * 32;
    int ib = (wid >> 2) * 32;

    int arow = (lid & 7) + ((lid >> 4) & 1) * 8;
    int acol = ((lid >> 3) & 1) * 8;
    int brow = (lid & 7) + ((lid >> 3) & 1) * 8;
    int bcol = ((lid >> 4) & 1) * 8;

    auto cp_chunk = [&](int ch, int buf) {
        int n0 = ch * CH;
        int nv = min(CH, N_TOK - n0);
#pragma unroll
        for (int i = 0; i < 4; i++) {
            int f = i * 512 + tid;
            int r = f >> 5, c4 = f & 31;
            int ok = (r < nv);
            const float* gu = U + (size_t)(n0 + (ok ? r : 0)) * C + 4 * c4;
            const float* gx = x + (size_t)(n0 + (ok ? r : 0)) * C + 4 * c4;
            uint32_t du = sb + G1_RAW + buf * 65536 + f * 16;
            int sz = ok ? 16 : 0;
            asm volatile("cp.async.cg.shared.global [%0], [%1], 16, %2;"
                         :: "r"(du), "l"(gu), "r"(sz) : "memory");
            asm volatile("cp.async.cg.shared.global [%0], [%1], 16, %2;"
                         :: "r"(du + 32768u), "l"(gx), "r"(sz) : "memory");
        }
        asm volatile("cp.async.commit_group;" ::: "memory");
    };

    float d[2][4][4];
#pragma unroll
    for (int mf = 0; mf < 2; mf++)
#pragma unroll
        for (int nf = 0; nf < 4; nf++)
#pragma unroll
            for (int q = 0; q < 4; q++) d[mf][nf][q] = 0.f;

    cp_chunk(bid, 0);
    int it = 0;
    for (int ch = bid; ch < NCH; ch += NBLK, it++) {
        int buf = it & 1;
        if (ch + NBLK < NCH) {
            cp_chunk(ch + NBLK, buf ^ 1);
            asm volatile("cp.async.wait_group 1;" ::: "memory");
        } else {
            asm volatile("cp.async.wait_group 0;" ::: "memory");
        }
        __syncthreads();

#pragma unroll
        for (int i = 0; i < 4; i++) {
            int f = i * 512 + tid;
            int r = f >> 5, c4 = f & 31;
            float4 vu = *(const float4*)(smem + G1_RAW + buf * 65536 + f * 16);
            float4 vx = *(const float4*)(smem + G1_RAW + buf * 65536 + 32768 + f * 16);
            uint2 H, L;
            split4(vu, H, L);
            *(uint2*)(smem + G1_UH + r * ROWB + 8 * c4) = H;
            *(uint2*)(smem + G1_UL + r * ROWB + 8 * c4) = L;
            split4(vx, H, L);
            *(uint2*)(smem + G1_XH + r * ROWB + 8 * c4) = H;
            *(uint2*)(smem + G1_XL + r * ROWB + 8 * c4) = L;
        }
        __syncthreads();

#pragma unroll
        for (int ks = 0; ks < 4; ks++) {
            int t0 = 16 * ks;
            uint32_t uh[2][4], ul[2][4];
#pragma unroll
            for (int mf = 0; mf < 2; mf++) {
                uint32_t off = ((t0 + arow) * ROWH + kb + mf * 16 + acol) * 2;
                ldsm4t(uh[mf][0], uh[mf][1], uh[mf][2], uh[mf][3],
                       sb + G1_UH + off);
                ldsm4t(ul[mf][0], ul[mf][1], ul[mf][2], ul[mf][3],
                       sb + G1_UL + off);
            }
#pragma unroll
            for (int p4 = 0; p4 < 2; p4++) {
                uint32_t off = ((t0 + brow) * ROWH + ib + p4 * 16 + bcol) * 2;
                uint32_t xh[4], xl[4];
                ldsm4t(xh[0], xh[1], xh[2], xh[3], sb + G1_XH + off);
                ldsm4t(xl[0], xl[1], xl[2], xl[3], sb + G1_XL + off);
#pragma unroll
                for (int mf = 0; mf < 2; mf++)
#pragma unroll
                    for (int n2 = 0; n2 < 2; n2++) {
                        float* dd = d[mf][2 * p4 + n2];
                        mma_f16(dd, uh[mf], &xh[2 * n2]);
                        mma_f16(dd, uh[mf], &xl[2 * n2]);
                        mma_f16(dd, ul[mf], &xh[2 * n2]);
                    }
            }
        }

        // export split U halves for gemm3
        {
            int n0 = ch * CH;
            int nv = min(CH, N_TOK - n0);
#pragma unroll
            for (int i = 0; i < 2; i++) {
                int f = i * 512 + tid;
                int r = f >> 4, c = f & 15;
                if (r < nv) {
                    uint4 vh = *(const uint4*)(smem + G1_UH + r * ROWB + 16 * c);
                    uint4 vl = *(const uint4*)(smem + G1_UL + r * ROWB + 16 * c);
                    *(uint4*)((char*)(g_Uhi + (size_t)(n0 + r) * C) + 16 * c) = vh;
                    *(uint4*)((char*)(g_Ulo + (size_t)(n0 + r) * C) + 16 * c) = vl;
                }
            }
        }
    }

    float* dst = g_part + (size_t)bid * (C * C);
#pragma unroll
    for (int mf = 0; mf < 2; mf++)
#pragma unroll
        for (int nf = 0; nf < 4; nf++) {
            int row = kb + mf * 16 + (lid >> 2);
            int col = ib + nf * 8 + 2 * (lid & 3);
            *(float2*)&dst[row * C + col] =
                make_float2(d[mf][nf][0], d[mf][nf][1]);
            *(float2*)&dst[(row + 8) * C + col] =
                make_float2(d[mf][nf][2], d[mf][nf][3]);
        }
}

// ---------------- 2) reduce partials -> g_spec -------------------------------
__global__ void k_rsum() {
    int j = blockIdx.x * 256 + threadIdx.x;
    float s0 = 0.f, s1 = 0.f, s2 = 0.f, s3 = 0.f;
#pragma unroll 1
    for (int b = 0; b < NBLK; b += 4) {
        s0 += g_part[(b + 0) * (C * C) + j];
        s1 += g_part[(b + 1) * (C * C) + j];
        s2 += g_part[(b + 2) * (C * C) + j];
        s3 += g_part[(b + 3) * (C * C) + j];
    }
    g_spec[j] = (s0 + s1) + (s2 + s3);
}

// ---------------- 3) mixed -> g_mixed[o][k] ----------------------------------
__global__ void __launch_bounds__(256) k_mixed_w(const float* __restrict__ coeffs) {
    int gw   = blockIdx.x * 8 + (threadIdx.x >> 5);
    int lane = threadIdx.x & 31;
    int o = gw >> 5, k0 = (gw & 31) * 4;
    float s[4];
#pragma unroll
    for (int kk = 0; kk < 4; kk++) {
        int k = k0 + kk;
        float4 a  = ((const float4*)(coeffs + (((size_t)o * C + k) << 7)))[lane];
        float4 bv = ((const float4*)(g_spec + (k << 7)))[lane];
        s[kk] = a.x * bv.x + a.y * bv.y + a.z * bv.z + a.w * bv.w;
    }
#pragma unroll
    for (int off = 16; off; off >>= 1)
#pragma unroll
        for (int kk = 0; kk < 4; kk++)
            s[kk] += __shfl_xor_sync(0xffffffffu, s[kk], off);
    if (lane == 0) {
#pragma unroll
        for (int kk = 0; kk < 4; kk++) g_mixed[(size_t)o * C + k0 + kk] = s[kk];
    }
}

// ---------------- 4) GEMM2: o-halved 256-thr blocks, 2 blocks/SM -------------
// Block (pair=bid>>1, oh=bid&1) computes o in [64*oh, 64*oh+64) for tiles
// t = pair, pair+148, ... ; A 34KB + B(hi/lo) 68KB -> occupancy 2.
#define A2_HI 0
#define A2_LO 17408
#define B2_HI 34816
#define B2_LO 69632
#define SM2_TOT 104448
#define SUM_THR (-15.0f)
#define SSTG2 68                  // staging stride (floats) = 272B row

__global__ void __launch_bounds__(256, 2) k_gemm3_p(float* __restrict__ out) {
    extern __shared__ char smem[];
    uint32_t sb = smem_u32(smem);
    __shared__ float red_m[4][64], red_s[4][64];
    int tid = threadIdx.x, wid = tid >> 5, lid = tid & 31;
    int pr  = blockIdx.x >> 1;          // pair id 0..147
    int oh  = blockIdx.x & 1;           // o-half
    int ob  = (wid & 1) * 32;           // warp o-base within half
    int nbw = (wid >> 1) * 32;          // warp n-base

    int arow_l = (lid & 7) + ((lid >> 3) & 1) * 8;
    int acol_l = ((lid >> 4) & 1) * 8;
    int brow_l = (lid & 7) + ((lid >> 4) & 1) * 8;
    int bcol_l = ((lid >> 3) & 1) * 8;

    // cp pre-split halves into B_HI/B_LO (whole 128-row tile)
    auto cp_tile = [&](int t) {
        int n0 = t * NT;
        int nvalid = min(NT, N_TOK - n0);
#pragma unroll
        for (int i = 0; i < 8; i++) {
            int f = i * 256 + tid;              // 0..2047
            int r = f >> 4, c = f & 15;         // row, 16B chunk
            int ok = (r < nvalid);
            const char* sh = (const char*)(g_Uhi + (size_t)(n0 + (ok ? r : 0)) * C) + 16 * c;
            const char* sl = (const char*)(g_Ulo + (size_t)(n0 + (ok ? r : 0)) * C) + 16 * c;
            uint32_t dh = sb + B2_HI + r * ROWB + 16 * c;
            int sz = ok ? 16 : 0;
            asm volatile("cp.async.cg.shared.global [%0], [%1], 16, %2;"
                         :: "r"(dh), "l"(sh), "r"(sz) : "memory");
            asm volatile("cp.async.cg.shared.global [%0], [%1], 16, %2;"
                         :: "r"(dh + (B2_LO - B2_HI)), "l"(sl), "r"(sz) : "memory");
        }
        asm volatile("cp.async.commit_group;" ::: "memory");
    };

    // A fill (this block's 64 o-rows)
#pragma unroll
    for (int i = 0; i < 8; i++) {
        int f = i * 256 + tid;                  // 0..2047
        int r = f >> 5, c4 = f & 31;            // r 0..63
        float4 v = ((const float4*)(g_mixed + (size_t)(oh * 64 + r) * C))[c4];
        uint2 H, L;
        split4(v, H, L);
        *(uint2*)(smem + A2_HI + r * ROWB + 8 * c4) = H;
        *(uint2*)(smem + A2_LO + r * ROWB + 8 * c4) = L;
    }

    float pm[4] = { -INFINITY, -INFINITY, -INFINITY, -INFINITY };
    float ps[4] = { 0.f, 0.f, 0.f, 0.f };

    for (int t = pr; t < NTILES; t += NBLK) {
        int n0 = t * NT;
        int nvalid = min(NT, N_TOK - n0);

        cp_tile(t);
        asm volatile("cp.async.wait_group 0;" ::: "memory");
        __syncthreads();                 // B visible (and A on first iter)

        float d[2][4][4];
#pragma unroll
        for (int mf = 0; mf < 2; mf++)
#pragma unroll
            for (int nf = 0; nf < 4; nf++)
#pragma unroll
                for (int q = 0; q < 4; q++) d[mf][nf][q] = 0.f;

        // fused 3-product loop
#pragma unroll
        for (int ks = 0; ks < 8; ks++) {
            int k0 = 16 * ks;
            uint32_t ah[2][4], al[2][4];
#pragma unroll
            for (int mf = 0; mf < 2; mf++) {
                uint32_t off = ((ob + mf * 16 + arow_l) * ROWH + k0 + acol_l) * 2;
                ldsm4(ah[mf][0], ah[mf][1], ah[mf][2], ah[mf][3], sb + A2_HI + off);
                ldsm4(al[mf][0], al[mf][1], al[mf][2], al[mf][3], sb + A2_LO + off);
            }
#pragma unroll
            for (int p4 = 0; p4 < 2; p4++) {
                uint32_t off = ((nbw + p4 * 16 + brow_l) * ROWH + k0 + bcol_l) * 2;
                uint32_t bh[4], bl[4];
                ldsm4(bh[0], bh[1], bh[2], bh[3], sb + B2_HI + off);
                ldsm4(bl[0], bl[1], bl[2], bl[3], sb + B2_LO + off);
#pragma unroll
                for (int mf = 0; mf < 2; mf++)
#pragma unroll
                    for (int n2 = 0; n2 < 2; n2++) {
                        float* dd = d[mf][2 * p4 + n2];
                        mma_f16(dd, ah[mf], &bh[2 * n2]);
                        mma_f16(dd, ah[mf], &bl[2 * n2]);
                        mma_f16(dd, al[mf], &bh[2 * n2]);
                    }
            }
        }
        __syncthreads();                 // MMA reads done; B retires

        // softmax partials (thresholded exp; padded logits = 0 vanish)
#pragma unroll
        for (int mf = 0; mf < 2; mf++)
#pragma unroll
            for (int h = 0; h < 2; h++) {
                int q = 2 * mf + h;
                float mt = -INFINITY;
#pragma unroll
                for (int nf = 0; nf < 4; nf++)
                    mt = fmaxf(mt, fmaxf(d[mf][nf][2 * h], d[mf][nf][2 * h + 1]));
                if (mt > pm[q]) {
                    ps[q] *= __expf(pm[q] - mt);
                    pm[q] = mt;
                }
                float m = pm[q];
#pragma unroll
                for (int nf = 0; nf < 4; nf++) {
                    float t0 = d[mf][nf][2 * h] - m;
                    float t1 = d[mf][nf][2 * h + 1] - m;
                    if (t0 > SUM_THR) ps[q] += __expf(t0);
                    if (t1 > SUM_THR) ps[q] += __expf(t1);
                }
            }

        // stage logits [n][o'] into retired B_HI region (128 x 68 floats)
        float* stg = (float*)(smem + B2_HI);
#pragma unroll
        for (int mf = 0; mf < 2; mf++)
#pragma unroll
            for (int nf = 0; nf < 4; nf++) {
                int n  = nbw + nf * 8 + 2 * (lid & 3);
                int o  = ob + mf * 16 + (lid >> 2);
                stg[n * SSTG2 + o]           = d[mf][nf][0];
                stg[(n + 1) * SSTG2 + o]     = d[mf][nf][1];
                stg[n * SSTG2 + o + 8]       = d[mf][nf][2];
                stg[(n + 1) * SSTG2 + o + 8] = d[mf][nf][3];
            }
        __syncthreads();

        // coalesced logit store: out[n][oh*64 + ...]
#pragma unroll
        for (int i = 0; i < 8; i++) {
            int f = i * 256 + tid;
            int r = f >> 4, c4 = f & 15;
            if (r < nvalid) {
                float4 v = *(const float4*)&stg[r * SSTG2 + 4 * c4];
                *(float4*)(out + (size_t)(n0 + r) * C + oh * 64 + 4 * c4) = v;
            }
        }
        __syncthreads();                 // stores' stg reads done before next cp
    }

    // ---- per-block softmax partials (o' in [0,64)) ----
#pragma unroll
    for (int off = 1; off <= 2; off <<= 1) {
#pragma unroll
        for (int q = 0; q < 4; q++) {
            float m2 = __shfl_xor_sync(0xffffffffu, pm[q], off);
            float s2 = __shfl_xor_sync(0xffffffffu, ps[q], off);
            comb(pm[q], ps[q], m2, s2);
        }
    }
    if ((lid & 3) == 0) {
#pragma unroll
        for (int q = 0; q < 4; q++) {
            int o = ((wid & 1) * 32) + (q >> 1) * 16 + (q & 1) * 8 + (lid >> 2);
            red_m[wid >> 1][o] = pm[q];
            red_s[wid >> 1][o] = ps[q];
        }
    }
    __syncthreads();
    if (tid < 64) {
        float M = red_m[0][tid], S = red_s[0][tid];
        comb(M, S, red_m[1][tid], red_s[1][tid]);
        comb(M, S, red_m[2][tid], red_s[2][tid]);
        comb(M, S, red_m[3][tid], red_s[3][tid]);
        g_pm[(size_t)(oh * 64 + tid) * NBLK + pr] = M;
        g_ps[(size_t)(oh * 64 + tid) * NBLK + pr] = S;
    }
}

// ---------------- 5) combine softmax partials --------------------------------
__global__ void k_softmax_par() {
    int o = blockIdx.x;
    float M = -INFINITY, S = 0.f;
    for (int b = threadIdx.x; b < NBLK; b += 256)
        comb(M, S, g_pm[(size_t)o * NBLK + b], g_ps[(size_t)o * NBLK + b]);
#pragma unroll
    for (int off = 16; off; off >>= 1) {
        float m2 = __shfl_xor_sync(0xffffffffu, M, off);
        float s2 = __shfl_xor_sync(0xffffffffu, S, off);
        comb(M, S, m2, s2);
    }
    __shared__ float sm[8], ss[8];
    int wq = threadIdx.x >> 5, lane = threadIdx.x & 31;
    if (lane == 0) { sm[wq] = M; ss[wq] = S; }
    __syncthreads();
    if (threadIdx.x == 0) {
#pragma unroll
        for (int i = 1; i < 8; i++) comb(sm[0], ss[0], sm[i], ss[i]);
        g_max[o]  = sm[0];
        g_sinv[o] = 1.0f / ss[0];
    }
}

// ---------------- 6) final: thresholded exp + normalize ----------------------
__global__ void k_final2(float* __restrict__ out) {
    int base = blockIdx.x * 512 + threadIdx.x;
#pragma unroll
    for (int h = 0; h < 2; h++) {
        int f = base + h * 256;
        float4 v = ((const float4*)out)[f];
        int og = f & 31;
        float4 M = ((const float4*)g_max)[og];
        float4 I = ((const float4*)g_sinv)[og];
        float t0 = v.x - M.x, t1 = v.y - M.y, t2 = v.z - M.z, t3 = v.w - M.w;
        v.x = (t0 > -87.f) ? __expf(t0) * I.x : 0.f;
        v.y = (t1 > -87.f) ? __expf(t1) * I.y : 0.f;
        v.z = (t2 > -87.f) ? __expf(t2) * I.z : 0.f;
        v.w = (t3 > -87.f) ? __expf(t3) * I.w : 0.f;
        ((float4*)out)[f] = v;
    }
}

// ---------------- launcher ---------------------------------------------------
extern "C" void kernel_launch(void* const* d_in, const int* in_sizes, int n_in,
                              void* d_out, int out_size) {
    const float* x      = (const float*)d_in[0];
    const float* U      = (const float*)d_in[1];
    const float* coeffs = (const float*)d_in[2];
    float* out = (float*)d_out;

    cudaFuncSetAttribute(k_gemm1_mma, cudaFuncAttributeMaxDynamicSharedMemorySize,
                         G1_SM);
    cudaFuncSetAttribute(k_gemm3_p, cudaFuncAttributeMaxDynamicSharedMemorySize,
                         SM2_TOT);

    k_gemm1_mma<<<NBLK, 512, G1_SM>>>(U, x);
    k_rsum<<<64, 256>>>();
    k_mixed_w<<<512, 256>>>(coeffs);
    k_gemm3_p<<<2 * NBLK, 256, SM2_TOT>>>(out);
    k_softmax_par<<<C, 256>>>();
    k_final2<<<N_TOK * C / 4 / 512, 256>>>(out);
}